// round 4
// baseline (speedup 1.0000x reference)
#include <cuda_runtime.h>

#define NY 256
#define NX 256
#define PML 20
#define PAD 22               // PML + FD_PAD
#define NYP 300              // NY + 2*PAD
#define NXP 300
#define DXH 5.0f
#define DT 0.0005f
#define NT 250
#define NSHOT 2
#define NSRC 8
#define NREC 64
#define PML_FREQ 25.0f
#define MAX_VEL 4000.0f

#define BX 32
#define BY 16

// ---------------- persistent device state (allocation-free scratch) ----------
__device__ float g_wf[2][NSHOT][NYP * NXP];     // ping-pong wavefield
__device__ float g_psiy[2][NSHOT][NYP * NXP];   // ping-pong (cross-block halo reads)
__device__ float g_psix[2][NSHOT][NYP * NXP];
__device__ float g_zetay[NSHOT][NYP * NXP];     // single buffer: owner-only RW
__device__ float g_zetax[NSHOT][NYP * NXP];
__device__ float g_v2dt2[NYP * NXP];
__device__ float g_a[NYP];                      // PML profiles (NYP==NXP, DY==DX)
__device__ float g_b[NYP];

// sanitized locations (filled by parse_kernel; robust to int32 vs int64 input)
__device__ int   g_src_y[NSHOT * NSRC], g_src_x[NSHOT * NSRC];
__device__ float g_src_scale[NSHOT * NSRC];     // v2dt2 at source
__device__ int   g_rec_y[NSHOT * NREC], g_rec_x[NSHOT * NREC];

__device__ __forceinline__ int clampi(int v, int lo, int hi) {
    return min(max(v, lo), hi);
}

// ---------------- parse locations (dtype-sniffing) ---------------------------
// If the harness passes int64 (little-endian, values in [0,256)), every odd
// int32 word is zero. For real int32 (y,x) pairs that is astronomically
// unlikely. One thread does everything (288 loads total).
__global__ void parse_kernel(const float* __restrict__ v,
                             const int* __restrict__ src_loc,
                             const int* __restrict__ rec_loc) {
    if (threadIdx.x != 0 || blockIdx.x != 0) return;

    // sniff src_loc dtype
    bool s64 = true;
    for (int i = 0; i < NSHOT * NSRC * 2; ++i)
        if (src_loc[2 * i + 1] != 0) { s64 = false; break; }
    bool r64 = true;
    for (int i = 0; i < NSHOT * NREC * 2; ++i)
        if (rec_loc[2 * i + 1] != 0) { r64 = false; break; }

    for (int i = 0; i < NSHOT * NSRC; ++i) {
        int y = s64 ? src_loc[4 * i + 0] : src_loc[2 * i + 0];
        int x = s64 ? src_loc[4 * i + 2] : src_loc[2 * i + 1];
        int sy = clampi(y + PAD, 0, NYP - 1);
        int sx = clampi(x + PAD, 0, NXP - 1);
        g_src_y[i] = sy; g_src_x[i] = sx;
        // v2dt2 at (sy,sx), computed directly from v (edge-padded)
        int cy = clampi(sy - PAD, 0, NY - 1);
        int cx = clampi(sx - PAD, 0, NX - 1);
        float vv = v[cy * NX + cx];
        g_src_scale[i] = vv * vv * (DT * DT);
    }
    for (int i = 0; i < NSHOT * NREC; ++i) {
        int y = r64 ? rec_loc[4 * i + 0] : rec_loc[2 * i + 0];
        int x = r64 ? rec_loc[4 * i + 2] : rec_loc[2 * i + 1];
        g_rec_y[i] = clampi(y + PAD, 0, NYP - 1);
        g_rec_x[i] = clampi(x + PAD, 0, NXP - 1);
    }
}

// ---------------- init: zero state, precompute v2dt2 + PML profiles ----------
__global__ void init_kernel(const float* __restrict__ v) {
    int idx = blockIdx.x * blockDim.x + threadIdx.x;
    if (idx >= NYP * NXP) return;
    int iy = idx / NXP, ix = idx % NXP;
    int cy = clampi(iy - PAD, 0, NY - 1);
    int cx = clampi(ix - PAD, 0, NX - 1);
    float vv = v[cy * NX + cx];
    g_v2dt2[idx] = vv * vv * (DT * DT);
#pragma unroll
    for (int s = 0; s < NSHOT; ++s) {
        g_wf[0][s][idx] = 0.f;  g_wf[1][s][idx] = 0.f;
        g_psiy[0][s][idx] = 0.f; g_psiy[1][s][idx] = 0.f;
        g_psix[0][s][idx] = 0.f; g_psix[1][s][idx] = 0.f;
        g_zetay[s][idx] = 0.f;   g_zetax[s][idx] = 0.f;
    }
    if (idx < NYP) {
        float fi = (float)idx;
        float frac = fmaxf((float)PAD - fi, fi - (float)(NYP - PAD - 1)) / (float)PML;
        frac = fminf(fmaxf(frac, 0.f), 1.f);
        float sigma_max = 3.f * MAX_VEL * logf(1000.f) / (2.f * PML * DXH);
        float sigma = sigma_max * frac * frac;
        float alpha = 3.14159265358979f * PML_FREQ * (1.f - frac);
        float b = expf(-(sigma + alpha) * DT);
        g_b[idx] = b;
        g_a[idx] = sigma / (sigma + alpha + 1e-9f) * (b - 1.f);
    }
}

// ---------------- fused per-timestep kernel --------------------------------
__global__ __launch_bounds__(BX * BY) void step_kernel(
    int t,
    const float* __restrict__ src_amp,
    float* __restrict__ out)
{
    const int cur = t & 1;
    const int shot = blockIdx.z;
    const int x0 = blockIdx.x * BX;
    const int y0 = blockIdx.y * BY;
    const int tx = threadIdx.x, ty = threadIdx.y;
    const int tid = ty * BX + tx;

    __shared__ float s_wf[BY + 8][BX + 8];
    __shared__ float s_py[BY + 4][BX];
    __shared__ float s_px[BY][BX + 4];
    __shared__ int   s_sy[NSRC], s_sx[NSRC];
    __shared__ float s_sv[NSRC];

    const float* __restrict__ wfc = g_wf[cur][shot];
    float* __restrict__ wfp       = g_wf[cur ^ 1][shot];   // holds wfm on entry
    const float* __restrict__ pyo = g_psiy[cur][shot];
    float* __restrict__ pyn       = g_psiy[cur ^ 1][shot];
    const float* __restrict__ pxo = g_psix[cur][shot];
    float* __restrict__ pxn       = g_psix[cur ^ 1][shot];
    float* __restrict__ zy        = g_zetay[shot];
    float* __restrict__ zx        = g_zetax[shot];

    // sources of this shot: v2dt2[src] * amp[t]
    if (tid < NSRC) {
        int k = shot * NSRC + tid;
        s_sy[tid] = g_src_y[k];
        s_sx[tid] = g_src_x[k];
        s_sv[tid] = g_src_scale[k] * src_amp[k * NT + t];
    }

    // wf tile with halo 4 (Dirichlet zero outside padded domain)
    for (int i = tid; i < (BY + 8) * (BX + 8); i += BX * BY) {
        int ly = i / (BX + 8), lx = i - ly * (BX + 8);
        int gy = y0 + ly - 4, gx = x0 + lx - 4;
        s_wf[ly][lx] = ((unsigned)gy < NYP && (unsigned)gx < NXP)
                           ? wfc[gy * NXP + gx] : 0.f;
    }

    // record previous step's receivers (wfc buffers are read-only this step)
    if (t > 0 && blockIdx.x == 0 && blockIdx.y == 0 && blockIdx.z == 0 &&
        tid < NSHOT * NREC) {
        out[tid * NT + (t - 1)] =
            g_wf[cur][tid / NREC][g_rec_y[tid] * NXP + g_rec_x[tid]];
    }
    __syncthreads();

    const float C1A = 0.083333336f;   // 1/12
    const float C1B = 0.6666667f;     // 2/3
    const float C2A = -0.083333336f;  // -1/12
    const float C2B = 1.3333334f;     // 4/3
    const float INVH = 0.2f;          // 1/DX
    const float INVH2 = 0.04f;        // 1/DX^2

    // psiy over rows [y0-2, y0+BY+2), interior rows written to new buffer
    for (int i = tid; i < (BY + 4) * BX; i += BX * BY) {
        int ly = i >> 5;          // /BX (BX==32)
        int lx = i & 31;
        int gy = y0 + ly - 2, gx = x0 + lx;
        float val = 0.f;
        if ((unsigned)gy < NYP && (unsigned)gx < NXP) {
            int sy_ = ly + 2, sx_ = lx + 4;
            float dw = (C1A * (s_wf[sy_ - 2][sx_] - s_wf[sy_ + 2][sx_]) +
                        C1B * (s_wf[sy_ + 1][sx_] - s_wf[sy_ - 1][sx_])) * INVH;
            val = g_b[gy] * pyo[gy * NXP + gx] + g_a[gy] * dw;
            if (ly >= 2 && ly < BY + 2) pyn[gy * NXP + gx] = val;
        }
        s_py[ly][lx] = val;
    }
    // psix over cols [x0-2, x0+BX+2)
    for (int i = tid; i < BY * (BX + 4); i += BX * BY) {
        int ly = i / (BX + 4), lx = i - ly * (BX + 4);
        int gy = y0 + ly, gx = x0 + lx - 2;
        float val = 0.f;
        if ((unsigned)gy < NYP && (unsigned)gx < NXP) {
            int sy_ = ly + 4, sx_ = lx + 2;
            float dw = (C1A * (s_wf[sy_][sx_ - 2] - s_wf[sy_][sx_ + 2]) +
                        C1B * (s_wf[sy_][sx_ + 1] - s_wf[sy_][sx_ - 1])) * INVH;
            val = g_b[gx] * pxo[gy * NXP + gx] + g_a[gx] * dw;
            if (lx >= 2 && lx < BX + 2) pxn[gy * NXP + gx] = val;
        }
        s_px[ly][lx] = val;
    }
    __syncthreads();

    int gy = y0 + ty, gx = x0 + tx;
    if (gy < NYP && gx < NXP) {
        int sy_ = ty + 4, sx_ = tx + 4;
        float w0 = s_wf[sy_][sx_];
        float d2y = (C2A * (s_wf[sy_ - 2][sx_] + s_wf[sy_ + 2][sx_]) +
                     C2B * (s_wf[sy_ - 1][sx_] + s_wf[sy_ + 1][sx_]) -
                     2.5f * w0) * INVH2;
        float d2x = (C2A * (s_wf[sy_][sx_ - 2] + s_wf[sy_][sx_ + 2]) +
                     C2B * (s_wf[sy_][sx_ - 1] + s_wf[sy_][sx_ + 1]) -
                     2.5f * w0) * INVH2;
        float dpy = (C1A * (s_py[ty][tx] - s_py[ty + 4][tx]) +
                     C1B * (s_py[ty + 3][tx] - s_py[ty + 1][tx])) * INVH;
        float dpx = (C1A * (s_px[ty][tx] - s_px[ty][tx + 4]) +
                     C1B * (s_px[ty][tx + 3] - s_px[ty][tx + 1])) * INVH;
        int g = gy * NXP + gx;
        float ayv = g_a[gy], byv = g_b[gy];
        float axv = g_a[gx], bxv = g_b[gx];
        float nzy = byv * zy[g] + ayv * (d2y + dpy);
        float nzx = bxv * zx[g] + axv * (d2x + dpx);
        zy[g] = nzy; zx[g] = nzx;
        float lap = d2y + d2x + dpy + dpx + nzy + nzx;
        float w = 2.f * w0 - wfp[g] + g_v2dt2[g] * lap;
#pragma unroll
        for (int s = 0; s < NSRC; ++s)
            if (gy == s_sy[s] && gx == s_sx[s]) w += s_sv[s];
        wfp[g] = w;
    }
}

// record receivers of the last timestep
__global__ void tail_kernel(float* __restrict__ out) {
    int tid = threadIdx.x;
    if (tid < NSHOT * NREC) {
        out[tid * NT + (NT - 1)] =
            g_wf[NT & 1][tid / NREC][g_rec_y[tid] * NXP + g_rec_x[tid]];
    }
}

extern "C" void kernel_launch(void* const* d_in, const int* in_sizes, int n_in,
                              void* d_out, int out_size) {
    // Identify inputs by element count (all four are distinct):
    //   v: 65536, src_amp: 4000, src_loc: 32, rec_loc: 256
    const float* v       = nullptr;
    const float* src_amp = nullptr;
    const int*   src_loc = nullptr;
    const int*   rec_loc = nullptr;
    for (int i = 0; i < n_in; ++i) {
        switch (in_sizes[i]) {
            case NY * NX:            v       = (const float*)d_in[i]; break;
            case NSHOT * NSRC * NT:  src_amp = (const float*)d_in[i]; break;
            case NSHOT * NSRC * 2:   src_loc = (const int*)d_in[i];   break;
            case NSHOT * NREC * 2:   rec_loc = (const int*)d_in[i];   break;
        }
    }
    float* out = (float*)d_out;

    parse_kernel<<<1, 32>>>(v, src_loc, rec_loc);
    init_kernel<<<(NYP * NXP + 255) / 256, 256>>>(v);

    dim3 block(BX, BY);
    dim3 grid((NXP + BX - 1) / BX, (NYP + BY - 1) / BY, NSHOT);
    for (int t = 0; t < NT; ++t)
        step_kernel<<<grid, block>>>(t, src_amp, out);

    tail_kernel<<<1, 128>>>(out);
}

// round 5
// speedup vs baseline: 1.1099x; 1.1099x over previous
#include <cuda_runtime.h>

#define NY 256
#define NX 256
#define PML 20
#define PAD 22               // PML + FD_PAD
#define NYP 300              // NY + 2*PAD
#define NXP 300
#define DXH 5.0f
#define DT 0.0005f
#define NT 250
#define NSHOT 2
#define NSRC 8
#define NREC 64
#define PML_FREQ 25.0f
#define MAX_VEL 4000.0f

#define BX 32
#define BY 16
#define GBX 10               // ceil(300/32)
#define GBY 19               // ceil(300/16)
#define NBLOCKS (GBX * GBY * NSHOT)   // 380, all co-resident (148 SMs * 3)

// ---------------- persistent device state (allocation-free scratch) ----------
__device__ float g_wf[2][NSHOT][NYP * NXP];     // ping-pong wavefield
__device__ float g_psiy[2][NSHOT][NYP * NXP];   // ping-pong psi (halo-read by neighbors)
__device__ float g_psix[2][NSHOT][NYP * NXP];
__device__ float g_v2dt2[NYP * NXP];
__device__ float g_a[NYP];                      // PML profiles (NYP==NXP, DY==DX)
__device__ float g_b[NYP];
__device__ unsigned g_count;                    // grid barrier (monotonic)

// sanitized locations (filled by parse_kernel; robust to int32 vs int64 input)
__device__ int   g_src_y[NSHOT * NSRC], g_src_x[NSHOT * NSRC];
__device__ float g_src_scale[NSHOT * NSRC];
__device__ int   g_rec_y[NSHOT * NREC], g_rec_x[NSHOT * NREC];

__device__ __forceinline__ int clampi(int v, int lo, int hi) {
    return min(max(v, lo), hi);
}

// ---------------- parse locations (dtype-sniffing) ---------------------------
__global__ void parse_kernel(const float* __restrict__ v,
                             const int* __restrict__ src_loc,
                             const int* __restrict__ rec_loc) {
    if (threadIdx.x != 0 || blockIdx.x != 0) return;

    bool s64 = true;
    for (int i = 0; i < NSHOT * NSRC * 2; ++i)
        if (src_loc[2 * i + 1] != 0) { s64 = false; break; }
    bool r64 = true;
    for (int i = 0; i < NSHOT * NREC * 2; ++i)
        if (rec_loc[2 * i + 1] != 0) { r64 = false; break; }

    for (int i = 0; i < NSHOT * NSRC; ++i) {
        int y = s64 ? src_loc[4 * i + 0] : src_loc[2 * i + 0];
        int x = s64 ? src_loc[4 * i + 2] : src_loc[2 * i + 1];
        int sy = clampi(y + PAD, 0, NYP - 1);
        int sx = clampi(x + PAD, 0, NXP - 1);
        g_src_y[i] = sy; g_src_x[i] = sx;
        int cy = clampi(sy - PAD, 0, NY - 1);
        int cx = clampi(sx - PAD, 0, NX - 1);
        float vv = v[cy * NX + cx];
        g_src_scale[i] = vv * vv * (DT * DT);
    }
    for (int i = 0; i < NSHOT * NREC; ++i) {
        int y = r64 ? rec_loc[4 * i + 0] : rec_loc[2 * i + 0];
        int x = r64 ? rec_loc[4 * i + 2] : rec_loc[2 * i + 1];
        g_rec_y[i] = clampi(y + PAD, 0, NYP - 1);
        g_rec_x[i] = clampi(x + PAD, 0, NXP - 1);
    }
}

// ---------------- init: zero state, precompute v2dt2 + PML profiles ----------
__global__ void init_kernel(const float* __restrict__ v) {
    int idx = blockIdx.x * blockDim.x + threadIdx.x;
    if (idx == 0) g_count = 0u;
    if (idx >= NYP * NXP) return;
    int iy = idx / NXP, ix = idx % NXP;
    int cy = clampi(iy - PAD, 0, NY - 1);
    int cx = clampi(ix - PAD, 0, NX - 1);
    float vv = v[cy * NX + cx];
    g_v2dt2[idx] = vv * vv * (DT * DT);
#pragma unroll
    for (int s = 0; s < NSHOT; ++s) {
        g_wf[0][s][idx] = 0.f;  g_wf[1][s][idx] = 0.f;
        g_psiy[0][s][idx] = 0.f; g_psiy[1][s][idx] = 0.f;
        g_psix[0][s][idx] = 0.f; g_psix[1][s][idx] = 0.f;
    }
    if (idx < NYP) {
        float fi = (float)idx;
        float frac = fmaxf((float)PAD - fi, fi - (float)(NYP - PAD - 1)) / (float)PML;
        frac = fminf(fmaxf(frac, 0.f), 1.f);
        float sigma_max = 3.f * MAX_VEL * logf(1000.f) / (2.f * PML * DXH);
        float sigma = sigma_max * frac * frac;
        float alpha = 3.14159265358979f * PML_FREQ * (1.f - frac);
        float b = expf(-(sigma + alpha) * DT);
        g_b[idx] = b;
        g_a[idx] = sigma / (sigma + alpha + 1e-9f) * (b - 1.f);
    }
}

// ---------------- grid barrier (monotonic ticket; all blocks co-resident) ----
__device__ __forceinline__ void grid_barrier(unsigned target, int tid) {
    __syncthreads();
    if (tid == 0) {
        __threadfence();
        atomicAdd(&g_count, 1u);
        while (true) {
            unsigned c;
            asm volatile("ld.acquire.gpu.global.u32 %0, [%1];"
                         : "=r"(c) : "l"(&g_count));
            if (c >= target) break;
            __nanosleep(40);
        }
    }
    __syncthreads();
}

// ---------------- persistent time-stepping kernel ---------------------------
__global__ __launch_bounds__(BX * BY, 3) void persist_kernel(
    const float* __restrict__ src_amp,
    float* __restrict__ out)
{
    const int shot = blockIdx.z;
    const int x0 = blockIdx.x * BX;
    const int y0 = blockIdx.y * BY;
    const int tx = threadIdx.x, ty = threadIdx.y;
    const int tid = ty * BX + tx;
    const int gy = y0 + ty, gx = x0 + tx;
    const bool active = (gy < NYP) && (gx < NXP);
    const int g = gy * NXP + gx;

    __shared__ float s_wf[BY + 8][BX + 8];
    __shared__ float s_py[BY + 4][BX];
    __shared__ float s_px[BY][BX + 4];
    __shared__ int   s_sy[NSRC], s_sx[NSRC];
    __shared__ float s_sv[NSRC];

    const float C1A = 0.083333336f;   // 1/12
    const float C1B = 0.6666667f;     // 2/3
    const float C2A = -0.083333336f;  // -1/12
    const float C2B = 1.3333334f;     // 4/3
    const float INVH = 0.2f;          // 1/DX
    const float INVH2 = 0.04f;        // 1/DX^2

    // per-cell recurrent state lives in registers (owner-only access)
    float wfm_r = 0.f;                // wf at t-1 (own cell)
    float zy_r = 0.f, zx_r = 0.f;     // zeta (own cell)
    float v2 = 0.f, ayv = 0.f, byv = 0.f, axv = 0.f, bxv = 0.f;
    if (active) {
        v2 = g_v2dt2[g];
        ayv = g_a[gy]; byv = g_b[gy];
        axv = g_a[gx]; bxv = g_b[gx];
    }

    // constant source coords for this shot
    if (tid < NSRC) {
        int k = shot * NSRC + tid;
        s_sy[tid] = g_src_y[k];
        s_sx[tid] = g_src_x[k];
    }

    for (int t = 0; t < NT; ++t) {
        const int cur = t & 1;
        const float* __restrict__ wfc = g_wf[cur][shot];
        float* __restrict__ wfp       = g_wf[cur ^ 1][shot];
        const float* __restrict__ pyo = g_psiy[cur][shot];
        float* __restrict__ pyn       = g_psiy[cur ^ 1][shot];
        const float* __restrict__ pxo = g_psix[cur][shot];
        float* __restrict__ pxn       = g_psix[cur ^ 1][shot];

        if (tid < NSRC) {
            int k = shot * NSRC + tid;
            s_sv[tid] = g_src_scale[k] * src_amp[k * NT + t];
        }

        // wf tile with halo 4 (Dirichlet zero outside padded domain)
        for (int i = tid; i < (BY + 8) * (BX + 8); i += BX * BY) {
            int ly = i / (BX + 8), lx = i - ly * (BX + 8);
            int yy = y0 + ly - 4, xx = x0 + lx - 4;
            s_wf[ly][lx] = ((unsigned)yy < NYP && (unsigned)xx < NXP)
                               ? wfc[yy * NXP + xx] : 0.f;
        }

        // record previous step's receivers (wfc buffers are read-only this step)
        if (t > 0 && blockIdx.x == 0 && blockIdx.y == 0 && blockIdx.z == 0 &&
            tid < NSHOT * NREC) {
            out[tid * NT + (t - 1)] =
                g_wf[cur][tid / NREC][g_rec_y[tid] * NXP + g_rec_x[tid]];
        }
        __syncthreads();

        // psiy over rows [y0-2, y0+BY+2), interior rows written to new buffer
        for (int i = tid; i < (BY + 4) * BX; i += BX * BY) {
            int ly = i >> 5;          // /BX (BX==32)
            int lx = i & 31;
            int yy = y0 + ly - 2, xx = x0 + lx;
            float val = 0.f;
            if ((unsigned)yy < NYP && (unsigned)xx < NXP) {
                int sy_ = ly + 2, sx_ = lx + 4;
                float dw = (C1A * (s_wf[sy_ - 2][sx_] - s_wf[sy_ + 2][sx_]) +
                            C1B * (s_wf[sy_ + 1][sx_] - s_wf[sy_ - 1][sx_])) * INVH;
                val = g_b[yy] * pyo[yy * NXP + xx] + g_a[yy] * dw;
                if (ly >= 2 && ly < BY + 2) pyn[yy * NXP + xx] = val;
            }
            s_py[ly][lx] = val;
        }
        // psix over cols [x0-2, x0+BX+2)
        for (int i = tid; i < BY * (BX + 4); i += BX * BY) {
            int ly = i / (BX + 4), lx = i - ly * (BX + 4);
            int yy = y0 + ly, xx = x0 + lx - 2;
            float val = 0.f;
            if ((unsigned)yy < NYP && (unsigned)xx < NXP) {
                int sy_ = ly + 4, sx_ = lx + 2;
                float dw = (C1A * (s_wf[sy_][sx_ - 2] - s_wf[sy_][sx_ + 2]) +
                            C1B * (s_wf[sy_][sx_ + 1] - s_wf[sy_][sx_ - 1])) * INVH;
                val = g_b[xx] * pxo[yy * NXP + xx] + g_a[xx] * dw;
                if (lx >= 2 && lx < BX + 2) pxn[yy * NXP + xx] = val;
            }
            s_px[ly][lx] = val;
        }
        __syncthreads();

        if (active) {
            int sy_ = ty + 4, sx_ = tx + 4;
            float w0 = s_wf[sy_][sx_];
            float d2y = (C2A * (s_wf[sy_ - 2][sx_] + s_wf[sy_ + 2][sx_]) +
                         C2B * (s_wf[sy_ - 1][sx_] + s_wf[sy_ + 1][sx_]) -
                         2.5f * w0) * INVH2;
            float d2x = (C2A * (s_wf[sy_][sx_ - 2] + s_wf[sy_][sx_ + 2]) +
                         C2B * (s_wf[sy_][sx_ - 1] + s_wf[sy_][sx_ + 1]) -
                         2.5f * w0) * INVH2;
            float dpy = (C1A * (s_py[ty][tx] - s_py[ty + 4][tx]) +
                         C1B * (s_py[ty + 3][tx] - s_py[ty + 1][tx])) * INVH;
            float dpx = (C1A * (s_px[ty][tx] - s_px[ty][tx + 4]) +
                         C1B * (s_px[ty][tx + 3] - s_px[ty][tx + 1])) * INVH;
            zy_r = byv * zy_r + ayv * (d2y + dpy);
            zx_r = bxv * zx_r + axv * (d2x + dpx);
            float lap = d2y + d2x + dpy + dpx + zy_r + zx_r;
            float w = 2.f * w0 - wfm_r + v2 * lap;
#pragma unroll
            for (int s = 0; s < NSRC; ++s)
                if (gy == s_sy[s] && gx == s_sx[s]) w += s_sv[s];
            wfp[g] = w;
            wfm_r = w0;
        }

        grid_barrier((unsigned)NBLOCKS * (unsigned)(t + 1), tid);
    }

    // record receivers of the last timestep (final wf is in g_wf[NT & 1])
    if (blockIdx.x == 0 && blockIdx.y == 0 && blockIdx.z == 0 &&
        tid < NSHOT * NREC) {
        out[tid * NT + (NT - 1)] =
            g_wf[NT & 1][tid / NREC][g_rec_y[tid] * NXP + g_rec_x[tid]];
    }
}

extern "C" void kernel_launch(void* const* d_in, const int* in_sizes, int n_in,
                              void* d_out, int out_size) {
    // Identify inputs by element count (all four are distinct):
    //   v: 65536, src_amp: 4000, src_loc: 32, rec_loc: 256
    const float* v       = nullptr;
    const float* src_amp = nullptr;
    const int*   src_loc = nullptr;
    const int*   rec_loc = nullptr;
    for (int i = 0; i < n_in; ++i) {
        switch (in_sizes[i]) {
            case NY * NX:            v       = (const float*)d_in[i]; break;
            case NSHOT * NSRC * NT:  src_amp = (const float*)d_in[i]; break;
            case NSHOT * NSRC * 2:   src_loc = (const int*)d_in[i];   break;
            case NSHOT * NREC * 2:   rec_loc = (const int*)d_in[i];   break;
        }
    }
    float* out = (float*)d_out;

    parse_kernel<<<1, 32>>>(v, src_loc, rec_loc);
    init_kernel<<<(NYP * NXP + 255) / 256, 256>>>(v);

    dim3 block(BX, BY);
    dim3 grid(GBX, GBY, NSHOT);
    persist_kernel<<<grid, block>>>(src_amp, out);
}

// round 6
// speedup vs baseline: 1.3215x; 1.1906x over previous
#include <cuda_runtime.h>

#define NY 256
#define NX 256
#define PML 20
#define PAD 22               // PML + FD_PAD
#define NYP 300              // NY + 2*PAD
#define NXP 300
#define DXH 5.0f
#define DT 0.0005f
#define NT 250
#define NSHOT 2
#define NSRC 8
#define NREC 64
#define PML_FREQ 25.0f
#define MAX_VEL 4000.0f

#define BX 32
#define BY 16
#define GBX 10               // ceil(300/32)
#define GBY 19               // ceil(300/16)
#define BLOCKS_PER_SHOT (GBX * GBY)      // 190
// total 380 blocks; with __launch_bounds__(512,3): 444 co-resident slots >= 380

// ---------------- persistent device state (allocation-free scratch) ----------
__device__ float g_wf[2][NSHOT][NYP * NXP];     // ping-pong wavefield
__device__ float g_psiy[2][NSHOT][NYP * NXP];   // ping-pong psi
__device__ float g_psix[2][NSHOT][NYP * NXP];
__device__ float g_v2dt2[NYP * NXP];
__device__ float g_a[NYP];                      // PML profiles (NYP==NXP, DY==DX)
__device__ float g_b[NYP];
__device__ unsigned g_count[NSHOT];             // per-shot barrier (monotonic)

// sanitized locations (filled by parse_kernel; robust to int32 vs int64 input)
__device__ int   g_src_y[NSHOT * NSRC], g_src_x[NSHOT * NSRC];
__device__ float g_src_scale[NSHOT * NSRC];
__device__ int   g_rec_y[NSHOT * NREC], g_rec_x[NSHOT * NREC];

__device__ __forceinline__ int clampi(int v, int lo, int hi) {
    return min(max(v, lo), hi);
}

// ---------------- parse locations (dtype-sniffing, parallel) -----------------
__global__ void parse_kernel(const float* __restrict__ v,
                             const int* __restrict__ src_loc,
                             const int* __restrict__ rec_loc) {
    __shared__ int s_not64, r_not64;
    int tid = threadIdx.x;
    if (tid == 0) { s_not64 = 0; r_not64 = 0; }
    __syncthreads();
    // int64 little-endian values in [0,256) -> every odd int32 word is zero
    if (tid < NSHOT * NSRC * 2 && src_loc[2 * tid + 1] != 0) atomicOr(&s_not64, 1);
    if (tid < NSHOT * NREC * 2 && rec_loc[2 * tid + 1] != 0) atomicOr(&r_not64, 1);
    __syncthreads();
    bool s64 = !s_not64, r64 = !r_not64;

    if (tid < NSHOT * NSRC) {
        int y = s64 ? src_loc[4 * tid + 0] : src_loc[2 * tid + 0];
        int x = s64 ? src_loc[4 * tid + 2] : src_loc[2 * tid + 1];
        int sy = clampi(y + PAD, 0, NYP - 1);
        int sx = clampi(x + PAD, 0, NXP - 1);
        g_src_y[tid] = sy; g_src_x[tid] = sx;
        int cy = clampi(sy - PAD, 0, NY - 1);
        int cx = clampi(sx - PAD, 0, NX - 1);
        float vv = v[cy * NX + cx];
        g_src_scale[tid] = vv * vv * (DT * DT);
    }
    if (tid < NSHOT * NREC) {
        int y = r64 ? rec_loc[4 * tid + 0] : rec_loc[2 * tid + 0];
        int x = r64 ? rec_loc[4 * tid + 2] : rec_loc[2 * tid + 1];
        g_rec_y[tid] = clampi(y + PAD, 0, NYP - 1);
        g_rec_x[tid] = clampi(x + PAD, 0, NXP - 1);
    }
}

// ---------------- init: zero state, precompute v2dt2 + PML profiles ----------
__global__ void init_kernel(const float* __restrict__ v) {
    int idx = blockIdx.x * blockDim.x + threadIdx.x;
    if (idx < NSHOT) g_count[idx] = 0u;
    if (idx >= NYP * NXP) return;
    int iy = idx / NXP, ix = idx % NXP;
    int cy = clampi(iy - PAD, 0, NY - 1);
    int cx = clampi(ix - PAD, 0, NX - 1);
    float vv = v[cy * NX + cx];
    g_v2dt2[idx] = vv * vv * (DT * DT);
#pragma unroll
    for (int s = 0; s < NSHOT; ++s) {
        g_wf[0][s][idx] = 0.f;  g_wf[1][s][idx] = 0.f;
        g_psiy[0][s][idx] = 0.f; g_psiy[1][s][idx] = 0.f;
        g_psix[0][s][idx] = 0.f; g_psix[1][s][idx] = 0.f;
    }
    if (idx < NYP) {
        float fi = (float)idx;
        float frac = fmaxf((float)PAD - fi, fi - (float)(NYP - PAD - 1)) / (float)PML;
        frac = fminf(fmaxf(frac, 0.f), 1.f);
        float sigma_max = 3.f * MAX_VEL * logf(1000.f) / (2.f * PML * DXH);
        float sigma = sigma_max * frac * frac;
        float alpha = 3.14159265358979f * PML_FREQ * (1.f - frac);
        float b = expf(-(sigma + alpha) * DT);
        g_b[idx] = b;
        g_a[idx] = sigma / (sigma + alpha + 1e-9f) * (b - 1.f);
    }
}

// ---------------- persistent time-stepping kernel ---------------------------
__global__ __launch_bounds__(BX * BY, 3) void persist_kernel(
    const float* __restrict__ src_amp,
    float* __restrict__ out)
{
    const int shot = blockIdx.z;
    const int x0 = blockIdx.x * BX;
    const int y0 = blockIdx.y * BY;
    const int tx = threadIdx.x, ty = threadIdx.y;
    const int tid = ty * BX + tx;
    const int gy = y0 + ty, gx = x0 + tx;
    const bool active = (gy < NYP) && (gx < NXP);
    const int g = gy * NXP + gx;

    __shared__ float s_wf[BY + 8][BX + 8];     // 24 x 40
    __shared__ float s_py[BY + 4][BX];         // 20 x 32
    __shared__ float s_px[BY][BX + 4];         // 16 x 36
    __shared__ int   s_sy[NSRC], s_sx[NSRC];
    __shared__ float s_sv[NSRC];
    __shared__ int   s_has_src;

    const float C1A = 0.083333336f;   // 1/12
    const float C1B = 0.6666667f;     // 2/3
    const float C2A = -0.083333336f;  // -1/12
    const float C2B = 1.3333334f;     // 4/3
    const float INVH = 0.2f;          // 1/DX
    const float INVH2 = 0.04f;        // 1/DX^2

    // per-cell recurrent state in registers (owner-only access)
    float wfm_r = 0.f, zy_r = 0.f, zx_r = 0.f;
    float v2 = 0.f, ayv = 0.f, byv = 0.f, axv = 0.f, bxv = 0.f;
    if (active) {
        v2 = g_v2dt2[g];
        ayv = g_a[gy]; byv = g_b[gy];
        axv = g_a[gx]; bxv = g_b[gx];
    }

    // source coords for this shot; does this block contain any source?
    if (tid == 0) s_has_src = 0;
    __syncthreads();
    if (tid < NSRC) {
        int k = shot * NSRC + tid;
        int sy = g_src_y[k], sx = g_src_x[k];
        s_sy[tid] = sy; s_sx[tid] = sx;
        if (sy >= y0 && sy < y0 + BY && sx >= x0 && sx < x0 + BX)
            atomicOr(&s_has_src, 1);
    }
    __syncthreads();
    const bool has_src = (s_has_src != 0);
    const bool is_rec_block = (blockIdx.x == 0 && blockIdx.y == 0);

    // --- psiy region geometry: rows ly in [0,20), cols tx ---
    // k=0: ly=ty (gy0 = y0+ty-2); k=1: ly=ty+16 (valid ty<4)
    const int py_gy0 = y0 + ty - 2;
    const int py_gy1 = y0 + ty + 14;
    const bool py_ok0 = ((unsigned)py_gy0 < NYP) && ((unsigned)gx < NXP);
    const bool py_ok1 = (ty < 4) && ((unsigned)py_gy1 < NYP) && ((unsigned)gx < NXP);
    const float py_a0 = py_ok0 ? g_a[py_gy0] : 0.f;
    const float py_b0 = py_ok0 ? g_b[py_gy0] : 0.f;
    const float py_a1 = py_ok1 ? g_a[py_gy1] : 0.f;
    const float py_b1 = py_ok1 ? g_b[py_gy1] : 0.f;

    // --- psix region geometry: rows ty, cols lx in [0,36) ---
    // m=0: lx=tx (gx0 = x0+tx-2); m=1: lx=tx+32 (valid tx<4)
    const int px_gx0 = x0 + tx - 2;
    const int px_gx1 = x0 + tx + 30;
    const bool px_ok0 = ((unsigned)gy < NYP) && ((unsigned)px_gx0 < NXP);
    const bool px_ok1 = (tx < 4) && ((unsigned)gy < NYP) && ((unsigned)px_gx1 < NXP);
    const float px_a0 = px_ok0 ? g_a[px_gx0] : 0.f;
    const float px_b0 = px_ok0 ? g_b[px_gx0] : 0.f;
    const float px_a1 = px_ok1 ? g_a[px_gx1] : 0.f;
    const float px_b1 = px_ok1 ? g_b[px_gx1] : 0.f;

    for (int t = 0; t < NT; ++t) {
        const int cur = t & 1;
        const float* __restrict__ wfc = g_wf[cur][shot];
        float* __restrict__ wfp       = g_wf[cur ^ 1][shot];
        const float* __restrict__ pyo = g_psiy[cur][shot];
        float* __restrict__ pyn       = g_psiy[cur ^ 1][shot];
        const float* __restrict__ pxo = g_psix[cur][shot];
        float* __restrict__ pxn       = g_psix[cur ^ 1][shot];

        // ---- prefetch phase (all global reads issued before first sync) ----
        if (tid < NSRC) {
            int k = shot * NSRC + tid;
            s_sv[tid] = g_src_scale[k] * src_amp[k * NT + t];
        }

        // psi-old prefetch (hides second L2 exposure under the halo load)
        float pyo0 = py_ok0 ? pyo[py_gy0 * NXP + gx] : 0.f;
        float pyo1 = py_ok1 ? pyo[py_gy1 * NXP + gx] : 0.f;
        float pxo0 = px_ok0 ? pxo[gy * NXP + px_gx0] : 0.f;
        float pxo1 = px_ok1 ? pxo[gy * NXP + px_gx1] : 0.f;

        // record previous step's receivers (own shot; wfc stable this step)
        if (t > 0 && is_rec_block && tid < NREC) {
            int k = shot * NREC + tid;
            out[k * NT + (t - 1)] = wfc[g_rec_y[k] * NXP + g_rec_x[k]];
        }

        // wf tile with halo 4 (Dirichlet zero outside padded domain),
        // division-free: ly = ty + 16k (ly<24), lx = tx + 32m (lx<40)
#pragma unroll
        for (int k = 0; k < 2; ++k) {
            int ly = ty + 16 * k;
            if (k == 0 || ty < 8) {
                int yy = y0 + ly - 4;
                bool yok = (unsigned)yy < NYP;
#pragma unroll
                for (int m = 0; m < 2; ++m) {
                    int lx = tx + 32 * m;
                    if (m == 0 || tx < 8) {
                        int xx = x0 + lx - 4;
                        s_wf[ly][lx] = (yok && (unsigned)xx < NXP)
                                           ? wfc[yy * NXP + xx] : 0.f;
                    }
                }
            }
        }
        __syncthreads();

        // ---- psi compute (pure ALU; inputs prefetched) ----
        {   // psiy k=0: ly=ty
            int sy_ = ty + 2, sx_ = tx + 4;
            float dw = (C1A * (s_wf[sy_ - 2][sx_] - s_wf[sy_ + 2][sx_]) +
                        C1B * (s_wf[sy_ + 1][sx_] - s_wf[sy_ - 1][sx_])) * INVH;
            float val = py_b0 * pyo0 + py_a0 * dw;
            if (!py_ok0) val = 0.f;
            s_py[ty][tx] = val;
            if (py_ok0 && ty >= 2) pyn[py_gy0 * NXP + gx] = val;
        }
        if (ty < 4) {  // psiy k=1: ly=ty+16
            int sy_ = ty + 18, sx_ = tx + 4;
            float dw = (C1A * (s_wf[sy_ - 2][sx_] - s_wf[sy_ + 2][sx_]) +
                        C1B * (s_wf[sy_ + 1][sx_] - s_wf[sy_ - 1][sx_])) * INVH;
            float val = py_b1 * pyo1 + py_a1 * dw;
            if (!py_ok1) val = 0.f;
            s_py[ty + 16][tx] = val;
            if (py_ok1 && ty < 2) pyn[py_gy1 * NXP + gx] = val;
        }
        {   // psix m=0: lx=tx
            int sy_ = ty + 4, sx_ = tx + 2;
            float dw = (C1A * (s_wf[sy_][sx_ - 2] - s_wf[sy_][sx_ + 2]) +
                        C1B * (s_wf[sy_][sx_ + 1] - s_wf[sy_][sx_ - 1])) * INVH;
            float val = px_b0 * pxo0 + px_a0 * dw;
            if (!px_ok0) val = 0.f;
            s_px[ty][tx] = val;
            if (px_ok0 && tx >= 2) pxn[gy * NXP + px_gx0] = val;
        }
        if (tx < 4) {  // psix m=1: lx=tx+32
            int sy_ = ty + 4, sx_ = tx + 34;
            float dw = (C1A * (s_wf[sy_][sx_ - 2] - s_wf[sy_][sx_ + 2]) +
                        C1B * (s_wf[sy_][sx_ + 1] - s_wf[sy_][sx_ - 1])) * INVH;
            float val = px_b1 * pxo1 + px_a1 * dw;
            if (!px_ok1) val = 0.f;
            s_px[ty][tx + 32] = val;
            if (px_ok1 && tx < 2) pxn[gy * NXP + px_gx1] = val;
        }
        __syncthreads();

        // ---- main update ----
        if (active) {
            int sy_ = ty + 4, sx_ = tx + 4;
            float w0 = s_wf[sy_][sx_];
            float d2y = (C2A * (s_wf[sy_ - 2][sx_] + s_wf[sy_ + 2][sx_]) +
                         C2B * (s_wf[sy_ - 1][sx_] + s_wf[sy_ + 1][sx_]) -
                         2.5f * w0) * INVH2;
            float d2x = (C2A * (s_wf[sy_][sx_ - 2] + s_wf[sy_][sx_ + 2]) +
                         C2B * (s_wf[sy_][sx_ - 1] + s_wf[sy_][sx_ + 1]) -
                         2.5f * w0) * INVH2;
            float dpy = (C1A * (s_py[ty][tx] - s_py[ty + 4][tx]) +
                         C1B * (s_py[ty + 3][tx] - s_py[ty + 1][tx])) * INVH;
            float dpx = (C1A * (s_px[ty][tx] - s_px[ty][tx + 4]) +
                         C1B * (s_px[ty][tx + 3] - s_px[ty][tx + 1])) * INVH;
            zy_r = byv * zy_r + ayv * (d2y + dpy);
            zx_r = bxv * zx_r + axv * (d2x + dpx);
            float lap = d2y + d2x + dpy + dpx + zy_r + zx_r;
            float w = 2.f * w0 - wfm_r + v2 * lap;
            if (has_src) {
#pragma unroll
                for (int s = 0; s < NSRC; ++s)
                    if (gy == s_sy[s] && gx == s_sx[s]) w += s_sv[s];
            }
            wfp[g] = w;
            wfm_r = w0;
        }

        // ---- per-shot grid barrier (monotonic counter) ----
        __syncthreads();
        if (tid == 0) {
            __threadfence();
            atomicAdd(&g_count[shot], 1u);
            unsigned target = (unsigned)BLOCKS_PER_SHOT * (unsigned)(t + 1);
            while (true) {
                unsigned c;
                asm volatile("ld.acquire.gpu.global.u32 %0, [%1];"
                             : "=r"(c) : "l"(&g_count[shot]));
                if (c >= target) break;
                __nanosleep(20);
            }
        }
        __syncthreads();
    }

    // record receivers of the last timestep (final wf is in g_wf[NT & 1])
    if (is_rec_block && tid < NREC) {
        int k = shot * NREC + tid;
        out[k * NT + (NT - 1)] =
            g_wf[NT & 1][shot][g_rec_y[k] * NXP + g_rec_x[k]];
    }
}

extern "C" void kernel_launch(void* const* d_in, const int* in_sizes, int n_in,
                              void* d_out, int out_size) {
    // Identify inputs by element count (all four are distinct):
    //   v: 65536, src_amp: 4000, src_loc: 32, rec_loc: 256
    const float* v       = nullptr;
    const float* src_amp = nullptr;
    const int*   src_loc = nullptr;
    const int*   rec_loc = nullptr;
    for (int i = 0; i < n_in; ++i) {
        switch (in_sizes[i]) {
            case NY * NX:            v       = (const float*)d_in[i]; break;
            case NSHOT * NSRC * NT:  src_amp = (const float*)d_in[i]; break;
            case NSHOT * NSRC * 2:   src_loc = (const int*)d_in[i];   break;
            case NSHOT * NREC * 2:   rec_loc = (const int*)d_in[i];   break;
        }
    }
    float* out = (float*)d_out;

    parse_kernel<<<1, 256>>>(v, src_loc, rec_loc);
    init_kernel<<<(NYP * NXP + 255) / 256, 256>>>(v);

    dim3 block(BX, BY);
    dim3 grid(GBX, GBY, NSHOT);
    persist_kernel<<<grid, block>>>(src_amp, out);
}

// round 9
// speedup vs baseline: 1.4988x; 1.1342x over previous
#include <cuda_runtime.h>

#define NY 256
#define NX 256
#define PML 20
#define PAD 22               // PML + FD_PAD
#define NYP 300              // NY + 2*PAD (logical padded domain)
#define NXP 300
#define DXH 5.0f
#define DT 0.0005f
#define NT 250
#define NSHOT 2
#define NSRC 8
#define NREC 64
#define PML_FREQ 25.0f
#define MAX_VEL 4000.0f

// ---- compute-domain padding: 320 x 320 cells, 4-cell zero guard ring ------
#define TSX 64               // tile width  (cells)
#define TSY 32               // tile height (cells)
#define GX2 5                // 5*64  = 320 >= 300
#define GY2 10               // 10*32 = 320 >= 300
#define BPS (GX2 * GY2)      // 50 blocks per shot; 100 total <= 148 SMs
#define OFF 4                // guard cells on each side
#define SX 336               // row stride (floats): 320 + 2*4 guards + pad
#define NROWS 328            // 320 + 2*4
#define FSZ (NROWS * SX)     // floats per field

#define IDX(y, x) (((y) + OFF) * SX + (x) + OFF)

// ---------------- persistent device state (allocation-free scratch) ----------
__device__ float g_wf[2][NSHOT][FSZ];
__device__ float g_psiy[2][NSHOT][FSZ];
__device__ float g_psix[2][NSHOT][FSZ];
__device__ float g_v2dt2[FSZ];
__device__ float g_a[NROWS];             // PML profiles over guard-padded coord
__device__ float g_b[NROWS];
__device__ unsigned g_count[NSHOT];      // per-shot barrier (monotonic)

__device__ int   g_src_y[NSHOT * NSRC], g_src_x[NSHOT * NSRC];
__device__ float g_src_scale[NSHOT * NSRC];
__device__ int   g_rec_y[NSHOT * NREC], g_rec_x[NSHOT * NREC];

__device__ __forceinline__ int clampi(int v, int lo, int hi) {
    return min(max(v, lo), hi);
}

// profile coefficient lookup in padded coords (y in [-4, 324))
__device__ __forceinline__ float A_(int y) { return g_a[y + OFF]; }
__device__ __forceinline__ float B_(int y) { return g_b[y + OFF]; }

// ---------------- parse locations (dtype-sniffing, parallel) -----------------
__global__ void parse_kernel(const float* __restrict__ v,
                             const int* __restrict__ src_loc,
                             const int* __restrict__ rec_loc) {
    __shared__ int s_not64, r_not64;
    int tid = threadIdx.x;
    if (tid == 0) { s_not64 = 0; r_not64 = 0; }
    __syncthreads();
    if (tid < NSHOT * NSRC * 2 && src_loc[2 * tid + 1] != 0) atomicOr(&s_not64, 1);
    if (tid < NSHOT * NREC * 2 && rec_loc[2 * tid + 1] != 0) atomicOr(&r_not64, 1);
    __syncthreads();
    bool s64 = !s_not64, r64 = !r_not64;

    if (tid < NSHOT * NSRC) {
        int y = s64 ? src_loc[4 * tid + 0] : src_loc[2 * tid + 0];
        int x = s64 ? src_loc[4 * tid + 2] : src_loc[2 * tid + 1];
        int sy = clampi(y + PAD, 0, NYP - 1);
        int sx = clampi(x + PAD, 0, NXP - 1);
        g_src_y[tid] = sy; g_src_x[tid] = sx;
        int cy = clampi(sy - PAD, 0, NY - 1);
        int cx = clampi(sx - PAD, 0, NX - 1);
        float vv = v[cy * NX + cx];
        g_src_scale[tid] = vv * vv * (DT * DT);
    }
    if (tid < NSHOT * NREC) {
        int y = r64 ? rec_loc[4 * tid + 0] : rec_loc[2 * tid + 0];
        int x = r64 ? rec_loc[4 * tid + 2] : rec_loc[2 * tid + 1];
        g_rec_y[tid] = clampi(y + PAD, 0, NYP - 1);
        g_rec_x[tid] = clampi(x + PAD, 0, NXP - 1);
    }
}

// ---------------- init: zero state, precompute v2dt2 + PML profiles ----------
__global__ void init_kernel(const float* __restrict__ v) {
    int idx = blockIdx.x * blockDim.x + threadIdx.x;
    if (idx < NSHOT) g_count[idx] = 0u;
    if (idx < NROWS) {
        int coord = idx - OFF;
        float a = 0.f, b = 0.f;
        if (coord >= 0 && coord < NYP) {
            float fi = (float)coord;
            float frac = fmaxf((float)PAD - fi, fi - (float)(NYP - PAD - 1)) / (float)PML;
            frac = fminf(fmaxf(frac, 0.f), 1.f);
            float sigma_max = 3.f * MAX_VEL * logf(1000.f) / (2.f * PML * DXH);
            float sigma = sigma_max * frac * frac;
            float alpha = 3.14159265358979f * PML_FREQ * (1.f - frac);
            b = expf(-(sigma + alpha) * DT);
            a = sigma / (sigma + alpha + 1e-9f) * (b - 1.f);
        }
        g_a[idx] = a;
        g_b[idx] = b;
    }
    if (idx >= FSZ) return;
    int iy = idx / SX - OFF, ix = idx % SX - OFF;
    float v2 = 0.f;
    if (iy >= 0 && iy < NYP && ix >= 0 && ix < NXP) {
        int cy = clampi(iy - PAD, 0, NY - 1);
        int cx = clampi(ix - PAD, 0, NX - 1);
        float vv = v[cy * NX + cx];
        v2 = vv * vv * (DT * DT);
    }
    g_v2dt2[idx] = v2;
#pragma unroll
    for (int s = 0; s < NSHOT; ++s) {
        g_wf[0][s][idx] = 0.f;  g_wf[1][s][idx] = 0.f;
        g_psiy[0][s][idx] = 0.f; g_psiy[1][s][idx] = 0.f;
        g_psix[0][s][idx] = 0.f; g_psix[1][s][idx] = 0.f;
    }
}

// ---------------- persistent time-stepping kernel ---------------------------
// 64x32 tile, 512 threads, 2x2 cells per thread. Guard ring makes every
// global access unconditional; cells outside the 300x300 logical domain have
// a=b=v2=0 and remain identically zero.
__global__ __launch_bounds__(512) void persist_kernel(
    const float* __restrict__ src_amp,
    float* __restrict__ out)
{
    const int shot = blockIdx.z;
    const int x0 = blockIdx.x * TSX;
    const int y0 = blockIdx.y * TSY;
    const int tx = threadIdx.x, ty = threadIdx.y;   // (32, 16)
    const int tid = ty * 32 + tx;

    const int gx0 = x0 + tx, gx1 = gx0 + 32;
    const int gy0 = y0 + ty, gy1 = gy0 + 16;

    __shared__ float s_wf[TSY + 8][TSX + 8];   // 40 x 72
    __shared__ float s_py[TSY + 4][TSX];       // 36 x 64  (row r <-> gy = y0+r-2)
    __shared__ float s_px[TSY][TSX + 4];       // 32 x 68  (col c <-> gx = x0+c-2)
    __shared__ int   s_sy[NSRC], s_sx[NSRC];
    __shared__ float s_sv[NSRC];
    __shared__ int   s_has_src;

    const float C1A = 0.083333336f;   // 1/12
    const float C1B = 0.6666667f;     // 2/3
    const float C2A = -0.083333336f;  // -1/12
    const float C2B = 1.3333334f;     // 4/3
    const float INVH = 0.2f;          // 1/DX
    const float INVH2 = 0.04f;        // 1/DX^2

    // ---- loop-invariant coefficients (registers) ----
    const float v2_00 = g_v2dt2[IDX(gy0, gx0)];
    const float v2_01 = g_v2dt2[IDX(gy0, gx1)];
    const float v2_10 = g_v2dt2[IDX(gy1, gx0)];
    const float v2_11 = g_v2dt2[IDX(gy1, gx1)];
    const float ay0 = A_(gy0), by0 = B_(gy0);
    const float ay1 = A_(gy1), by1 = B_(gy1);
    const float ax0 = A_(gx0), bx0 = B_(gx0);
    const float ax1 = A_(gx1), bx1 = B_(gx1);

    // psiy row slots: r_i = y0 + ty - 2 + 16*i  (i=2 valid only ty<4)
    const int r0 = y0 + ty - 2, r1 = r0 + 16, r2 = r0 + 32;
    const float pa0 = A_(r0), pb0 = B_(r0);
    const float pa1 = A_(r1), pb1 = B_(r1);
    const float pa2 = (ty < 4) ? A_(r2) : 0.f;
    const float pb2 = (ty < 4) ? B_(r2) : 0.f;

    // psix col slots: c_j = x0 + tx - 2 + 32*j  (j=2 valid only tx<4)
    const int c0 = x0 + tx - 2, c1 = c0 + 32, c2 = c0 + 64;
    const float qa0 = A_(c0), qb0 = B_(c0);
    const float qa1 = A_(c1), qb1 = B_(c1);
    const float qa2 = (tx < 4) ? A_(c2) : 0.f;
    const float qb2 = (tx < 4) ? B_(c2) : 0.f;

    // recurrent per-cell state (registers)
    float wfm00 = 0.f, wfm01 = 0.f, wfm10 = 0.f, wfm11 = 0.f;
    float zy00 = 0.f, zy01 = 0.f, zy10 = 0.f, zy11 = 0.f;
    float zx00 = 0.f, zx01 = 0.f, zx10 = 0.f, zx11 = 0.f;

    if (tid == 0) s_has_src = 0;
    __syncthreads();
    if (tid < NSRC) {
        int k = shot * NSRC + tid;
        int sy = g_src_y[k], sx = g_src_x[k];
        s_sy[tid] = sy; s_sx[tid] = sx;
        if (sy >= y0 && sy < y0 + TSY && sx >= x0 && sx < x0 + TSX)
            atomicOr(&s_has_src, 1);
    }
    __syncthreads();
    const bool has_src = (s_has_src != 0);
    const bool is_rec_block = (blockIdx.x == 0 && blockIdx.y == 0);

    for (int t = 0; t < NT; ++t) {
        const int cur = t & 1;
        const float* __restrict__ wfc = g_wf[cur][shot];
        float* __restrict__ wfp       = g_wf[cur ^ 1][shot];
        const float* __restrict__ pyo = g_psiy[cur][shot];
        float* __restrict__ pyn       = g_psiy[cur ^ 1][shot];
        const float* __restrict__ pxo = g_psix[cur][shot];
        float* __restrict__ pxn       = g_psix[cur ^ 1][shot];

        // ---- prefetch: psi-old, source amp, receiver gathers ----
        if (tid < NSRC) {
            int k = shot * NSRC + tid;
            s_sv[tid] = g_src_scale[k] * src_amp[k * NT + t];
        }
        float py00 = pyo[IDX(r0, gx0)], py01 = pyo[IDX(r0, gx1)];
        float py10 = pyo[IDX(r1, gx0)], py11 = pyo[IDX(r1, gx1)];
        float py20 = (ty < 4) ? pyo[IDX(r2, gx0)] : 0.f;
        float py21 = (ty < 4) ? pyo[IDX(r2, gx1)] : 0.f;
        float px00 = pxo[IDX(gy0, c0)], px01 = pxo[IDX(gy1, c0)];
        float px10 = pxo[IDX(gy0, c1)], px11 = pxo[IDX(gy1, c1)];
        float px20 = (tx < 4) ? pxo[IDX(gy0, c2)] : 0.f;
        float px21 = (tx < 4) ? pxo[IDX(gy1, c2)] : 0.f;

        if (t > 0 && is_rec_block && tid < NREC) {
            int k = shot * NREC + tid;
            out[k * NT + (t - 1)] = wfc[IDX(g_rec_y[k], g_rec_x[k])];
        }

        // ---- wf halo tile (unconditional; guard ring absorbs edges) ----
        // base points at (y0-4, x0-4)
        const float* __restrict__ base = wfc + y0 * SX + x0;
#pragma unroll
        for (int i = 0; i < 3; ++i) {
            int ly = ty + 16 * i;
            if (i < 2 || ty < 8) {
#pragma unroll
                for (int j = 0; j < 3; ++j) {
                    int lx = tx + 32 * j;
                    if (j < 2 || tx < 8)
                        s_wf[ly][lx] = base[ly * SX + lx];
                }
            }
        }
        __syncthreads();

        // ---- psiy: rows r_i, cols gx0/gx1 ----
        {
            int lxa = tx, lxb = tx + 32;
            // slot 0: smem row ty
            {
                int ly = ty;
                float dwa = (C1A * (s_wf[ly][lxa + 4] - s_wf[ly + 4][lxa + 4]) +
                             C1B * (s_wf[ly + 3][lxa + 4] - s_wf[ly + 1][lxa + 4])) * INVH;
                float dwb = (C1A * (s_wf[ly][lxb + 4] - s_wf[ly + 4][lxb + 4]) +
                             C1B * (s_wf[ly + 3][lxb + 4] - s_wf[ly + 1][lxb + 4])) * INVH;
                float va = pb0 * py00 + pa0 * dwa;
                float vb = pb0 * py01 + pa0 * dwb;
                s_py[ly][lxa] = va; s_py[ly][lxb] = vb;
                if (ty >= 2) { pyn[IDX(r0, gx0)] = va; pyn[IDX(r0, gx1)] = vb; }
            }
            // slot 1: smem row ty+16 (always interior write)
            {
                int ly = ty + 16;
                float dwa = (C1A * (s_wf[ly][lxa + 4] - s_wf[ly + 4][lxa + 4]) +
                             C1B * (s_wf[ly + 3][lxa + 4] - s_wf[ly + 1][lxa + 4])) * INVH;
                float dwb = (C1A * (s_wf[ly][lxb + 4] - s_wf[ly + 4][lxb + 4]) +
                             C1B * (s_wf[ly + 3][lxb + 4] - s_wf[ly + 1][lxb + 4])) * INVH;
                float va = pb1 * py10 + pa1 * dwa;
                float vb = pb1 * py11 + pa1 * dwb;
                s_py[ly][lxa] = va; s_py[ly][lxb] = vb;
                pyn[IDX(r1, gx0)] = va; pyn[IDX(r1, gx1)] = vb;
            }
            // slot 2: smem row ty+32 (ty<4)
            if (ty < 4) {
                int ly = ty + 32;
                float dwa = (C1A * (s_wf[ly][lxa + 4] - s_wf[ly + 4][lxa + 4]) +
                             C1B * (s_wf[ly + 3][lxa + 4] - s_wf[ly + 1][lxa + 4])) * INVH;
                float dwb = (C1A * (s_wf[ly][lxb + 4] - s_wf[ly + 4][lxb + 4]) +
                             C1B * (s_wf[ly + 3][lxb + 4] - s_wf[ly + 1][lxb + 4])) * INVH;
                float va = pb2 * py20 + pa2 * dwa;
                float vb = pb2 * py21 + pa2 * dwb;
                s_py[ly][lxa] = va; s_py[ly][lxb] = vb;
                if (ty < 2) { pyn[IDX(r2, gx0)] = va; pyn[IDX(r2, gx1)] = vb; }
            }
        }
        // ---- psix: cols c_j, rows gy0/gy1 ----
        {
            int rya = ty + 4, ryb = ty + 20;       // s_wf rows for gy0, gy1
            // slot 0: smem col tx
            {
                int lx = tx;
                float dwa = (C1A * (s_wf[rya][lx] - s_wf[rya][lx + 4]) +
                             C1B * (s_wf[rya][lx + 3] - s_wf[rya][lx + 1])) * INVH;
                float dwb = (C1A * (s_wf[ryb][lx] - s_wf[ryb][lx + 4]) +
                             C1B * (s_wf[ryb][lx + 3] - s_wf[ryb][lx + 1])) * INVH;
                float va = qb0 * px00 + qa0 * dwa;
                float vb = qb0 * px01 + qa0 * dwb;
                s_px[ty][lx] = va; s_px[ty + 16][lx] = vb;
                if (tx >= 2) { pxn[IDX(gy0, c0)] = va; pxn[IDX(gy1, c0)] = vb; }
            }
            // slot 1: smem col tx+32 (always interior write)
            {
                int lx = tx + 32;
                float dwa = (C1A * (s_wf[rya][lx] - s_wf[rya][lx + 4]) +
                             C1B * (s_wf[rya][lx + 3] - s_wf[rya][lx + 1])) * INVH;
                float dwb = (C1A * (s_wf[ryb][lx] - s_wf[ryb][lx + 4]) +
                             C1B * (s_wf[ryb][lx + 3] - s_wf[ryb][lx + 1])) * INVH;
                float va = qb1 * px10 + qa1 * dwa;
                float vb = qb1 * px11 + qa1 * dwb;
                s_px[ty][lx] = va; s_px[ty + 16][lx] = vb;
                pxn[IDX(gy0, c1)] = va; pxn[IDX(gy1, c1)] = vb;
            }
            // slot 2: smem col tx+64 (tx<4)
            if (tx < 4) {
                int lx = tx + 64;
                float dwa = (C1A * (s_wf[rya][lx] - s_wf[rya][lx + 4]) +
                             C1B * (s_wf[rya][lx + 3] - s_wf[rya][lx + 1])) * INVH;
                float dwb = (C1A * (s_wf[ryb][lx] - s_wf[ryb][lx + 4]) +
                             C1B * (s_wf[ryb][lx + 3] - s_wf[ryb][lx + 1])) * INVH;
                float va = qb2 * px20 + qa2 * dwa;
                float vb = qb2 * px21 + qa2 * dwb;
                s_px[ty][lx] = va; s_px[ty + 16][lx] = vb;
                if (tx < 2) { pxn[IDX(gy0, c2)] = va; pxn[IDX(gy1, c2)] = vb; }
            }
        }
        __syncthreads();

        // ---- main update: 4 cells per thread ----
#pragma unroll
        for (int i = 0; i < 2; ++i) {
#pragma unroll
            for (int j = 0; j < 2; ++j) {
                const int sy = ty + 4 + 16 * i, sx = tx + 4 + 32 * j;
                const int pr = ty + 16 * i, pc = tx + 32 * j;
                const int gy = (i == 0) ? gy0 : gy1;
                const int gx = (j == 0) ? gx0 : gx1;
                float w0 = s_wf[sy][sx];
                float d2y = (C2A * (s_wf[sy - 2][sx] + s_wf[sy + 2][sx]) +
                             C2B * (s_wf[sy - 1][sx] + s_wf[sy + 1][sx]) -
                             2.5f * w0) * INVH2;
                float d2x = (C2A * (s_wf[sy][sx - 2] + s_wf[sy][sx + 2]) +
                             C2B * (s_wf[sy][sx - 1] + s_wf[sy][sx + 1]) -
                             2.5f * w0) * INVH2;
                float dpy = (C1A * (s_py[pr][pc] - s_py[pr + 4][pc]) +
                             C1B * (s_py[pr + 3][pc] - s_py[pr + 1][pc])) * INVH;
                float dpx = (C1A * (s_px[pr][pc] - s_px[pr][pc + 4]) +
                             C1B * (s_px[pr][pc + 3] - s_px[pr][pc + 1])) * INVH;
                float ayv = (i == 0) ? ay0 : ay1, byv = (i == 0) ? by0 : by1;
                float axv = (j == 0) ? ax0 : ax1, bxv = (j == 0) ? bx0 : bx1;
                float &zyr = (i == 0) ? ((j == 0) ? zy00 : zy01)
                                      : ((j == 0) ? zy10 : zy11);
                float &zxr = (i == 0) ? ((j == 0) ? zx00 : zx01)
                                      : ((j == 0) ? zx10 : zx11);
                float &wfmr = (i == 0) ? ((j == 0) ? wfm00 : wfm01)
                                       : ((j == 0) ? wfm10 : wfm11);
                zyr = byv * zyr + ayv * (d2y + dpy);
                zxr = bxv * zxr + axv * (d2x + dpx);
                float lap = d2y + d2x + dpy + dpx + zyr + zxr;
                float v2 = (i == 0) ? ((j == 0) ? v2_00 : v2_01)
                                    : ((j == 0) ? v2_10 : v2_11);
                float w = 2.f * w0 - wfmr + v2 * lap;
                if (has_src) {
#pragma unroll
                    for (int s = 0; s < NSRC; ++s)
                        if (gy == s_sy[s] && gx == s_sx[s]) w += s_sv[s];
                }
                wfp[IDX(gy, gx)] = w;
                wfmr = w0;
            }
        }

        // ---- per-shot grid barrier (monotonic counter) ----
        __syncthreads();
        if (tid == 0) {
            __threadfence();
            atomicAdd(&g_count[shot], 1u);
            unsigned target = (unsigned)BPS * (unsigned)(t + 1);
            while (true) {
                unsigned c;
                asm volatile("ld.acquire.gpu.global.u32 %0, [%1];"
                             : "=r"(c) : "l"(&g_count[shot]));
                if (c >= target) break;
                __nanosleep(20);
            }
        }
        __syncthreads();
    }

    // record receivers of the last timestep (final wf is in g_wf[NT & 1])
    if (is_rec_block && tid < NREC) {
        int k = shot * NREC + tid;
        out[k * NT + (NT - 1)] =
            g_wf[NT & 1][shot][IDX(g_rec_y[k], g_rec_x[k])];
    }
}

extern "C" void kernel_launch(void* const* d_in, const int* in_sizes, int n_in,
                              void* d_out, int out_size) {
    // Identify inputs by element count (all four are distinct):
    //   v: 65536, src_amp: 4000, src_loc: 32, rec_loc: 256
    const float* v       = nullptr;
    const float* src_amp = nullptr;
    const int*   src_loc = nullptr;
    const int*   rec_loc = nullptr;
    for (int i = 0; i < n_in; ++i) {
        switch (in_sizes[i]) {
            case NY * NX:            v       = (const float*)d_in[i]; break;
            case NSHOT * NSRC * NT:  src_amp = (const float*)d_in[i]; break;
            case NSHOT * NSRC * 2:   src_loc = (const int*)d_in[i];   break;
            case NSHOT * NREC * 2:   rec_loc = (const int*)d_in[i];   break;
        }
    }
    float* out = (float*)d_out;

    parse_kernel<<<1, 256>>>(v, src_loc, rec_loc);
    init_kernel<<<(FSZ + 255) / 256, 256>>>(v);

    dim3 block(32, 16);
    dim3 grid(GX2, GY2, NSHOT);
    persist_kernel<<<grid, block>>>(src_amp, out);
}

// round 11
// speedup vs baseline: 1.5731x; 1.0496x over previous
#include <cuda_runtime.h>

#define NY 256
#define NX 256
#define PML 20
#define PAD 22               // PML + FD_PAD
#define NYP 300              // NY + 2*PAD (logical padded domain)
#define NXP 300
#define DXH 5.0f
#define DT 0.0005f
#define NT 250
#define NSHOT 2
#define NSRC 8
#define NREC 64
#define PML_FREQ 25.0f
#define MAX_VEL 4000.0f

// ---- compute-domain padding: 320 x 320 cells, 4-cell zero guard ring ------
#define TSX 64               // tile width  (cells)
#define TSY 32               // tile height (cells)
#define GX2 5                // 5*64  = 320 >= 300
#define GY2 10               // 10*32 = 320 >= 300
#define BPS (GX2 * GY2)      // 50 blocks per shot; 100 total <= 148 SMs
#define OFF 4                // guard cells on each side
#define SX 336               // row stride (floats): 320 + 2*4 guards + pad
#define NROWS 328            // 320 + 2*4
#define FSZ (NROWS * SX)     // floats per field

#define IDX(y, x) (((y) + OFF) * SX + (x) + OFF)

// ---------------- persistent device state (allocation-free scratch) ----------
__device__ float g_wf[2][NSHOT][FSZ];    // only wf needs global (halo-shared)
__device__ float g_v2dt2[FSZ];
__device__ float g_a[NROWS];             // PML profiles over guard-padded coord
__device__ float g_b[NROWS];
__device__ unsigned g_count[NSHOT];      // per-shot barrier (monotonic)

__device__ int   g_src_y[NSHOT * NSRC], g_src_x[NSHOT * NSRC];
__device__ float g_src_scale[NSHOT * NSRC];
__device__ int   g_rec_y[NSHOT * NREC], g_rec_x[NSHOT * NREC];

__device__ __forceinline__ int clampi(int v, int lo, int hi) {
    return min(max(v, lo), hi);
}

// profile coefficient lookup in padded coords (y in [-4, 324))
__device__ __forceinline__ float A_(int y) { return g_a[y + OFF]; }
__device__ __forceinline__ float B_(int y) { return g_b[y + OFF]; }

// ---------------- parse locations (dtype-sniffing, parallel) -----------------
__global__ void parse_kernel(const float* __restrict__ v,
                             const int* __restrict__ src_loc,
                             const int* __restrict__ rec_loc) {
    __shared__ int s_not64, r_not64;
    int tid = threadIdx.x;
    if (tid == 0) { s_not64 = 0; r_not64 = 0; }
    __syncthreads();
    if (tid < NSHOT * NSRC * 2 && src_loc[2 * tid + 1] != 0) atomicOr(&s_not64, 1);
    if (tid < NSHOT * NREC * 2 && rec_loc[2 * tid + 1] != 0) atomicOr(&r_not64, 1);
    __syncthreads();
    bool s64 = !s_not64, r64 = !r_not64;

    if (tid < NSHOT * NSRC) {
        int y = s64 ? src_loc[4 * tid + 0] : src_loc[2 * tid + 0];
        int x = s64 ? src_loc[4 * tid + 2] : src_loc[2 * tid + 1];
        int sy = clampi(y + PAD, 0, NYP - 1);
        int sx = clampi(x + PAD, 0, NXP - 1);
        g_src_y[tid] = sy; g_src_x[tid] = sx;
        int cy = clampi(sy - PAD, 0, NY - 1);
        int cx = clampi(sx - PAD, 0, NX - 1);
        float vv = v[cy * NX + cx];
        g_src_scale[tid] = vv * vv * (DT * DT);
    }
    if (tid < NSHOT * NREC) {
        int y = r64 ? rec_loc[4 * tid + 0] : rec_loc[2 * tid + 0];
        int x = r64 ? rec_loc[4 * tid + 2] : rec_loc[2 * tid + 1];
        g_rec_y[tid] = clampi(y + PAD, 0, NYP - 1);
        g_rec_x[tid] = clampi(x + PAD, 0, NXP - 1);
    }
}

// ---------------- init: zero wf, precompute v2dt2 + PML profiles -------------
__global__ void init_kernel(const float* __restrict__ v) {
    int idx = blockIdx.x * blockDim.x + threadIdx.x;
    if (idx < NSHOT) g_count[idx] = 0u;
    if (idx < NROWS) {
        int coord = idx - OFF;
        float a = 0.f, b = 0.f;
        if (coord >= 0 && coord < NYP) {
            float fi = (float)coord;
            float frac = fmaxf((float)PAD - fi, fi - (float)(NYP - PAD - 1)) / (float)PML;
            frac = fminf(fmaxf(frac, 0.f), 1.f);
            float sigma_max = 3.f * MAX_VEL * logf(1000.f) / (2.f * PML * DXH);
            float sigma = sigma_max * frac * frac;
            float alpha = 3.14159265358979f * PML_FREQ * (1.f - frac);
            b = expf(-(sigma + alpha) * DT);
            a = sigma / (sigma + alpha + 1e-9f) * (b - 1.f);
        }
        g_a[idx] = a;
        g_b[idx] = b;
    }
    if (idx >= FSZ) return;
    int iy = idx / SX - OFF, ix = idx % SX - OFF;
    float v2 = 0.f;
    if (iy >= 0 && iy < NYP && ix >= 0 && ix < NXP) {
        int cy = clampi(iy - PAD, 0, NY - 1);
        int cx = clampi(ix - PAD, 0, NX - 1);
        float vv = v[cy * NX + cx];
        v2 = vv * vv * (DT * DT);
    }
    g_v2dt2[idx] = v2;
#pragma unroll
    for (int s = 0; s < NSHOT; ++s) {
        g_wf[0][s][idx] = 0.f;  g_wf[1][s][idx] = 0.f;
    }
}

// ---------------- persistent time-stepping kernel ---------------------------
// 64x32 tile, 512 threads, 2x2 cells per thread. psi lives ENTIRELY in smem:
// each block recomputes tile+halo2 psi every step; neighbors never exchange
// psi (identical recomputation from identical inputs, induction from zero).
// Only wf goes through global memory.
__global__ __launch_bounds__(512) void persist_kernel(
    const float* __restrict__ src_amp,
    float* __restrict__ out)
{
    const int shot = blockIdx.z;
    const int x0 = blockIdx.x * TSX;
    const int y0 = blockIdx.y * TSY;
    const int tx = threadIdx.x, ty = threadIdx.y;   // (32, 16)
    const int tid = ty * 32 + tx;

    const int gx0 = x0 + tx, gx1 = gx0 + 32;
    const int gy0 = y0 + ty, gy1 = gy0 + 16;

    __shared__ float s_wf[TSY + 8][TSX + 8];   // 40 x 72
    __shared__ float s_py[TSY + 4][TSX];       // 36 x 64  (row r <-> gy = y0+r-2)
    __shared__ float s_px[TSY][TSX + 4];       // 32 x 68  (col c <-> gx = x0+c-2)
    __shared__ int   s_sy[NSRC], s_sx[NSRC];
    __shared__ float s_sv[NSRC];
    __shared__ int   s_has_src;

    const float C1A = 0.083333336f;   // 1/12
    const float C1B = 0.6666667f;     // 2/3
    const float C2A = -0.083333336f;  // -1/12
    const float C2B = 1.3333334f;     // 4/3
    const float INVH = 0.2f;          // 1/DX
    const float INVH2 = 0.04f;        // 1/DX^2

    // ---- loop-invariant coefficients (registers) ----
    const float v2_00 = g_v2dt2[IDX(gy0, gx0)];
    const float v2_01 = g_v2dt2[IDX(gy0, gx1)];
    const float v2_10 = g_v2dt2[IDX(gy1, gx0)];
    const float v2_11 = g_v2dt2[IDX(gy1, gx1)];
    const float ay0 = A_(gy0), by0 = B_(gy0);
    const float ay1 = A_(gy1), by1 = B_(gy1);
    const float ax0 = A_(gx0), bx0 = B_(gx0);
    const float ax1 = A_(gx1), bx1 = B_(gx1);

    // psiy row slots: r_i = y0 + ty - 2 + 16*i  (i=2 valid only ty<4)
    const float pa0 = A_(y0 + ty - 2),  pb0 = B_(y0 + ty - 2);
    const float pa1 = A_(y0 + ty + 14), pb1 = B_(y0 + ty + 14);
    const float pa2 = (ty < 4) ? A_(y0 + ty + 30) : 0.f;
    const float pb2 = (ty < 4) ? B_(y0 + ty + 30) : 0.f;

    // psix col slots: c_j = x0 + tx - 2 + 32*j  (j=2 valid only tx<4)
    const float qa0 = A_(x0 + tx - 2),  qb0 = B_(x0 + tx - 2);
    const float qa1 = A_(x0 + tx + 30), qb1 = B_(x0 + tx + 30);
    const float qa2 = (tx < 4) ? A_(x0 + tx + 62) : 0.f;
    const float qb2 = (tx < 4) ? B_(x0 + tx + 62) : 0.f;

    // recurrent per-cell state (registers)
    float wfm00 = 0.f, wfm01 = 0.f, wfm10 = 0.f, wfm11 = 0.f;
    float zy00 = 0.f, zy01 = 0.f, zy10 = 0.f, zy11 = 0.f;
    float zx00 = 0.f, zx01 = 0.f, zx10 = 0.f, zx11 = 0.f;

    // ---- zero psi smem (initial condition) + source setup ----
    if (tid == 0) s_has_src = 0;
    {
        s_py[ty][tx] = 0.f;       s_py[ty][tx + 32] = 0.f;
        s_py[ty + 16][tx] = 0.f;  s_py[ty + 16][tx + 32] = 0.f;
        if (ty < 4) { s_py[ty + 32][tx] = 0.f; s_py[ty + 32][tx + 32] = 0.f; }
        s_px[ty][tx] = 0.f;       s_px[ty][tx + 32] = 0.f;
        s_px[ty + 16][tx] = 0.f;  s_px[ty + 16][tx + 32] = 0.f;
        if (tx < 4) { s_px[ty][tx + 64] = 0.f; s_px[ty + 16][tx + 64] = 0.f; }
    }
    __syncthreads();
    if (tid < NSRC) {
        int k = shot * NSRC + tid;
        int sy = g_src_y[k], sx = g_src_x[k];
        s_sy[tid] = sy; s_sx[tid] = sx;
        if (sy >= y0 && sy < y0 + TSY && sx >= x0 && sx < x0 + TSX)
            atomicOr(&s_has_src, 1);
    }
    __syncthreads();
    const bool has_src = (s_has_src != 0);
    const bool is_rec_block = (blockIdx.x == 0 && blockIdx.y == 0);

    for (int t = 0; t < NT; ++t) {
        const int cur = t & 1;
        const float* __restrict__ wfc = g_wf[cur][shot];
        float* __restrict__ wfp       = g_wf[cur ^ 1][shot];

        // ---- prefetch: source amp, receiver gathers ----
        if (tid < NSRC) {
            int k = shot * NSRC + tid;
            s_sv[tid] = g_src_scale[k] * src_amp[k * NT + t];
        }
        if (t > 0 && is_rec_block && tid < NREC) {
            int k = shot * NREC + tid;
            out[k * NT + (t - 1)] = wfc[IDX(g_rec_y[k], g_rec_x[k])];
        }

        // ---- wf halo tile (unconditional; guard ring absorbs edges) ----
        const float* __restrict__ base = wfc + y0 * SX + x0;   // (y0-4, x0-4)
#pragma unroll
        for (int i = 0; i < 3; ++i) {
            int ly = ty + 16 * i;
            if (i < 2 || ty < 8) {
#pragma unroll
                for (int j = 0; j < 3; ++j) {
                    int lx = tx + 32 * j;
                    if (j < 2 || tx < 8)
                        s_wf[ly][lx] = base[ly * SX + lx];
                }
            }
        }
        __syncthreads();

        // ---- psi update in smem (each slot owned by exactly one thread) ----
        {
            int lxa = tx, lxb = tx + 32;
            {   // psiy slot 0: smem row ty
                int ly = ty;
                float dwa = (C1A * (s_wf[ly][lxa + 4] - s_wf[ly + 4][lxa + 4]) +
                             C1B * (s_wf[ly + 3][lxa + 4] - s_wf[ly + 1][lxa + 4])) * INVH;
                float dwb = (C1A * (s_wf[ly][lxb + 4] - s_wf[ly + 4][lxb + 4]) +
                             C1B * (s_wf[ly + 3][lxb + 4] - s_wf[ly + 1][lxb + 4])) * INVH;
                s_py[ly][lxa] = pb0 * s_py[ly][lxa] + pa0 * dwa;
                s_py[ly][lxb] = pb0 * s_py[ly][lxb] + pa0 * dwb;
            }
            {   // psiy slot 1: smem row ty+16
                int ly = ty + 16;
                float dwa = (C1A * (s_wf[ly][lxa + 4] - s_wf[ly + 4][lxa + 4]) +
                             C1B * (s_wf[ly + 3][lxa + 4] - s_wf[ly + 1][lxa + 4])) * INVH;
                float dwb = (C1A * (s_wf[ly][lxb + 4] - s_wf[ly + 4][lxb + 4]) +
                             C1B * (s_wf[ly + 3][lxb + 4] - s_wf[ly + 1][lxb + 4])) * INVH;
                s_py[ly][lxa] = pb1 * s_py[ly][lxa] + pa1 * dwa;
                s_py[ly][lxb] = pb1 * s_py[ly][lxb] + pa1 * dwb;
            }
            if (ty < 4) {   // psiy slot 2: smem row ty+32
                int ly = ty + 32;
                float dwa = (C1A * (s_wf[ly][lxa + 4] - s_wf[ly + 4][lxa + 4]) +
                             C1B * (s_wf[ly + 3][lxa + 4] - s_wf[ly + 1][lxa + 4])) * INVH;
                float dwb = (C1A * (s_wf[ly][lxb + 4] - s_wf[ly + 4][lxb + 4]) +
                             C1B * (s_wf[ly + 3][lxb + 4] - s_wf[ly + 1][lxb + 4])) * INVH;
                s_py[ly][lxa] = pb2 * s_py[ly][lxa] + pa2 * dwa;
                s_py[ly][lxb] = pb2 * s_py[ly][lxb] + pa2 * dwb;
            }
        }
        {
            int rya = ty + 4, ryb = ty + 20;       // s_wf rows for gy0, gy1
            {   // psix slot 0: smem col tx
                int lx = tx;
                float dwa = (C1A * (s_wf[rya][lx] - s_wf[rya][lx + 4]) +
                             C1B * (s_wf[rya][lx + 3] - s_wf[rya][lx + 1])) * INVH;
                float dwb = (C1A * (s_wf[ryb][lx] - s_wf[ryb][lx + 4]) +
                             C1B * (s_wf[ryb][lx + 3] - s_wf[ryb][lx + 1])) * INVH;
                s_px[ty][lx]      = qb0 * s_px[ty][lx]      + qa0 * dwa;
                s_px[ty + 16][lx] = qb0 * s_px[ty + 16][lx] + qa0 * dwb;
            }
            {   // psix slot 1: smem col tx+32
                int lx = tx + 32;
                float dwa = (C1A * (s_wf[rya][lx] - s_wf[rya][lx + 4]) +
                             C1B * (s_wf[rya][lx + 3] - s_wf[rya][lx + 1])) * INVH;
                float dwb = (C1A * (s_wf[ryb][lx] - s_wf[ryb][lx + 4]) +
                             C1B * (s_wf[ryb][lx + 3] - s_wf[ryb][lx + 1])) * INVH;
                s_px[ty][lx]      = qb1 * s_px[ty][lx]      + qa1 * dwa;
                s_px[ty + 16][lx] = qb1 * s_px[ty + 16][lx] + qa1 * dwb;
            }
            if (tx < 4) {   // psix slot 2: smem col tx+64
                int lx = tx + 64;
                float dwa = (C1A * (s_wf[rya][lx] - s_wf[rya][lx + 4]) +
                             C1B * (s_wf[rya][lx + 3] - s_wf[rya][lx + 1])) * INVH;
                float dwb = (C1A * (s_wf[ryb][lx] - s_wf[ryb][lx + 4]) +
                             C1B * (s_wf[ryb][lx + 3] - s_wf[ryb][lx + 1])) * INVH;
                s_px[ty][lx]      = qb2 * s_px[ty][lx]      + qa2 * dwa;
                s_px[ty + 16][lx] = qb2 * s_px[ty + 16][lx] + qa2 * dwb;
            }
        }
        __syncthreads();

        // ---- main update: 4 cells per thread ----
#pragma unroll
        for (int i = 0; i < 2; ++i) {
#pragma unroll
            for (int j = 0; j < 2; ++j) {
                const int sy = ty + 4 + 16 * i, sx = tx + 4 + 32 * j;
                const int pr = ty + 16 * i, pc = tx + 32 * j;
                const int gy = (i == 0) ? gy0 : gy1;
                const int gx = (j == 0) ? gx0 : gx1;
                float w0 = s_wf[sy][sx];
                float d2y = (C2A * (s_wf[sy - 2][sx] + s_wf[sy + 2][sx]) +
                             C2B * (s_wf[sy - 1][sx] + s_wf[sy + 1][sx]) -
                             2.5f * w0) * INVH2;
                float d2x = (C2A * (s_wf[sy][sx - 2] + s_wf[sy][sx + 2]) +
                             C2B * (s_wf[sy][sx - 1] + s_wf[sy][sx + 1]) -
                             2.5f * w0) * INVH2;
                float dpy = (C1A * (s_py[pr][pc] - s_py[pr + 4][pc]) +
                             C1B * (s_py[pr + 3][pc] - s_py[pr + 1][pc])) * INVH;
                float dpx = (C1A * (s_px[pr][pc] - s_px[pr][pc + 4]) +
                             C1B * (s_px[pr][pc + 3] - s_px[pr][pc + 1])) * INVH;
                float ayv = (i == 0) ? ay0 : ay1, byv = (i == 0) ? by0 : by1;
                float axv = (j == 0) ? ax0 : ax1, bxv = (j == 0) ? bx0 : bx1;
                float &zyr = (i == 0) ? ((j == 0) ? zy00 : zy01)
                                      : ((j == 0) ? zy10 : zy11);
                float &zxr = (i == 0) ? ((j == 0) ? zx00 : zx01)
                                      : ((j == 0) ? zx10 : zx11);
                float &wfmr = (i == 0) ? ((j == 0) ? wfm00 : wfm01)
                                       : ((j == 0) ? wfm10 : wfm11);
                zyr = byv * zyr + ayv * (d2y + dpy);
                zxr = bxv * zxr + axv * (d2x + dpx);
                float lap = d2y + d2x + dpy + dpx + zyr + zxr;
                float v2 = (i == 0) ? ((j == 0) ? v2_00 : v2_01)
                                    : ((j == 0) ? v2_10 : v2_11);
                float w = 2.f * w0 - wfmr + v2 * lap;
                if (has_src) {
#pragma unroll
                    for (int s = 0; s < NSRC; ++s)
                        if (gy == s_sy[s] && gx == s_sx[s]) w += s_sv[s];
                }
                wfp[IDX(gy, gx)] = w;
                wfmr = w0;
            }
        }

        // ---- per-shot grid barrier (monotonic counter) ----
        __syncthreads();
        if (tid == 0) {
            __threadfence();
            atomicAdd(&g_count[shot], 1u);
            unsigned target = (unsigned)BPS * (unsigned)(t + 1);
            while (true) {
                unsigned c;
                asm volatile("ld.acquire.gpu.global.u32 %0, [%1];"
                             : "=r"(c) : "l"(&g_count[shot]));
                if (c >= target) break;
                __nanosleep(20);
            }
        }
        __syncthreads();
    }

    // record receivers of the last timestep (final wf is in g_wf[NT & 1])
    if (is_rec_block && tid < NREC) {
        int k = shot * NREC + tid;
        out[k * NT + (NT - 1)] =
            g_wf[NT & 1][shot][IDX(g_rec_y[k], g_rec_x[k])];
    }
}

extern "C" void kernel_launch(void* const* d_in, const int* in_sizes, int n_in,
                              void* d_out, int out_size) {
    // Identify inputs by element count (all four are distinct):
    //   v: 65536, src_amp: 4000, src_loc: 32, rec_loc: 256
    const float* v       = nullptr;
    const float* src_amp = nullptr;
    const int*   src_loc = nullptr;
    const int*   rec_loc = nullptr;
    for (int i = 0; i < n_in; ++i) {
        switch (in_sizes[i]) {
            case NY * NX:            v       = (const float*)d_in[i]; break;
            case NSHOT * NSRC * NT:  src_amp = (const float*)d_in[i]; break;
            case NSHOT * NSRC * 2:   src_loc = (const int*)d_in[i];   break;
            case NSHOT * NREC * 2:   rec_loc = (const int*)d_in[i];   break;
        }
    }
    float* out = (float*)d_out;

    parse_kernel<<<1, 256>>>(v, src_loc, rec_loc);
    init_kernel<<<(FSZ + 255) / 256, 256>>>(v);

    dim3 block(32, 16);
    dim3 grid(GX2, GY2, NSHOT);
    persist_kernel<<<grid, block>>>(src_amp, out);
}